// round 2
// baseline (speedup 1.0000x reference)
#include <cuda_runtime.h>

// SurfEval: NURBS surface evaluation.
// B=8, M=N=64, P=Q=3, GRID=512, DIM=3.
// Inputs (metadata order):
//   d_in[0] ctrl_pts : float32 [B, M, N, 4]   (xyz*w, w)
//   d_in[1] uspan    : int32   [GRID]
//   d_in[2] vspan    : int32   [GRID]
//   d_in[3] Nu       : float32 [GRID, 4]
//   d_in[4] Nv       : float32 [GRID, 4]
// Output: float32 [B, GRID, GRID, 3]

#define BB    8
#define MM    64
#define NN    64
#define GRIDD 512

__global__ __launch_bounds__(512)
void surf_eval_kernel(const float* __restrict__ ctrl,
                      const int*   __restrict__ uspan,
                      const int*   __restrict__ vspan,
                      const float* __restrict__ Nu,
                      const float* __restrict__ Nv,
                      float*       __restrict__ out)
{
    __shared__ float4 su_s[NN];          // Su[n][0..3] for this (b,g)
    __shared__ float  row_s[GRIDD * 3];  // staged output row (6 KB)

    const int g = blockIdx.x;            // u grid index
    const int b = blockIdx.y;            // batch
    const int t = threadIdx.x;           // 0..511

    // Hoist Phase-2 operand loads ABOVE the barrier so their DRAM/L2 latency
    // overlaps the Phase-1 contraction instead of serializing after it.
    const int   h  = t;
    const int   sv = vspan[h];                                   // in [3, 63]
    const float4 nv = *reinterpret_cast<const float4*>(Nv + 4 * h);

    // ---- Phase 1: u-direction contraction into shared memory ----
    // Su[n][d] = sum_r Nu[g][r] * ctrl[b][uspan[g]-3+r][n][d]
    if (t < NN * 4) {
        const int    su = uspan[g];                              // in [3, 63]
        const float4 nu = *reinterpret_cast<const float4*>(Nu + 4 * g);
        // thread t -> flattened (n,d) = t; row stride = NN*4 floats
        const float* base = ctrl + ((size_t)b * MM + (su - 3)) * (NN * 4);
        float acc = nu.x * base[t]
                  + nu.y * base[t + 1 * NN * 4]
                  + nu.z * base[t + 2 * NN * 4]
                  + nu.w * base[t + 3 * NN * 4];
        reinterpret_cast<float*>(su_s)[t] = acc;
    }
    __syncthreads();

    // ---- Phase 2: v-direction contraction, one thread per h ----
    const float4 p0 = su_s[sv - 3];
    const float4 p1 = su_s[sv - 2];
    const float4 p2 = su_s[sv - 1];
    const float4 p3 = su_s[sv - 0];

    float x = nv.x * p0.x + nv.y * p1.x + nv.z * p2.x + nv.w * p3.x;
    float y = nv.x * p0.y + nv.y * p1.y + nv.z * p2.y + nv.w * p3.y;
    float z = nv.x * p0.z + nv.y * p1.z + nv.z * p2.z + nv.w * p3.z;
    float w = nv.x * p0.w + nv.y * p1.w + nv.z * p2.w + nv.w * p3.w;

    const float inv = 1.0f / w;

    // stride-3 smem writes: gcd(3,32)=1 -> conflict-free
    row_s[h * 3 + 0] = x * inv;
    row_s[h * 3 + 1] = y * inv;
    row_s[h * 3 + 2] = z * inv;
    __syncthreads();

    // ---- Phase 3: coalesced float4 flush of the 6 KB row ----
    // row base byte offset = (b*GRID+g)*GRID*3*4 = multiple of 6144 -> 16B aligned
    float4* orow = reinterpret_cast<float4*>(
        out + (((size_t)b * GRIDD + g) * GRIDD) * 3);
    if (t < (GRIDD * 3) / 4) {           // 384 float4 stores
        orow[t] = reinterpret_cast<const float4*>(row_s)[t];
    }
}

extern "C" void kernel_launch(void* const* d_in, const int* in_sizes, int n_in,
                              void* d_out, int out_size)
{
    const float* ctrl  = (const float*)d_in[0];
    const int*   uspan = (const int*)  d_in[1];
    const int*   vspan = (const int*)  d_in[2];
    const float* Nu    = (const float*)d_in[3];
    const float* Nv    = (const float*)d_in[4];
    float*       out   = (float*)d_out;

    dim3 grid(GRIDD, BB);   // 512 x 8 = 4096 CTAs
    surf_eval_kernel<<<grid, 512>>>(ctrl, uspan, vspan, Nu, Nv, out);
}